// round 1
// baseline (speedup 1.0000x reference)
#include <cuda_runtime.h>
#include <math.h>

#define BB 8
#define HH 64
#define WW 64
#define WF 33
#define CC 1024
#define SPEC (BB*HH*WF*CC)

// Spectral scratch (static device allocations are allowed)
__device__ float g_Ar[SPEC];
__device__ float g_Ai[SPEC];
__device__ float g_Br[SPEC];
__device__ float g_Bi[SPEC];

__device__ __forceinline__ void make_root(float2* root, int t) {
    if (t < 64) {
        float s, c;
        sincosf(6.2831853071795864769f * (float)t / 64.0f, &s, &c);
        root[t] = make_float2(c, s);
    }
}

__device__ __forceinline__ float softshrink(float v) {
    return v > 0.01f ? v - 0.01f : (v < -0.01f ? v + 0.01f : 0.0f);
}

// ---------------------------------------------------------------------------
// K1: rfft along W (real -> 33 complex bins). Per (b,h) slab, 128-channel tile.
// A[b][h][kw][c] = sum_w x[b][h][w][c] * e^{-2pi i kw w/64}
// ---------------------------------------------------------------------------
__global__ void __launch_bounds__(256) k_row_rfft(const float* __restrict__ x) {
    __shared__ float2 sx[64 * 64];   // [w][c2]  (128 channels as 64 float2)
    __shared__ float2 root[64];
    int t = threadIdx.x;
    make_root(root, t);
    int slab = blockIdx.y;           // b*64 + h
    int c0 = blockIdx.x * 128;
    const float* xp = x + (size_t)slab * (64 * 1024) + c0;
    float4* sx4 = (float4*)sx;
    for (int f = t; f < 2048; f += 256) {       // 64 rows * 32 float4
        int w = f >> 5, q = f & 31;
        sx4[f] = *(const float4*)(xp + w * 1024 + q * 4);
    }
    __syncthreads();
    int c2 = t & 63;
    int kq = t >> 6;                  // 4 k-groups: 9,8,8,8 bins
    int kbeg = (kq == 0) ? 0 : (8 * kq + 1);
    int kend = 8 * kq + 9;
    for (int k = kbeg; k < kend; k++) {
        float arx = 0.f, ary = 0.f, aix = 0.f, aiy = 0.f;
        int j = 0;
        #pragma unroll
        for (int w = 0; w < 64; w++) {
            float2 tw = root[j];
            float2 xv = sx[w * 64 + c2];
            arx += xv.x * tw.x; ary += xv.y * tw.x;
            aix -= xv.x * tw.y; aiy -= xv.y * tw.y;
            j = (j + k) & 63;
        }
        size_t o = ((size_t)slab * 33 + k) * 1024 + c0 + 2 * c2;
        *(float2*)(g_Ar + o) = make_float2(arx, ary);
        *(float2*)(g_Ai + o) = make_float2(aix, aiy);
    }
}

// ---------------------------------------------------------------------------
// K2/K5: complex 64-point DFT along H. Forward (A->B, e^{-i}, *1/64) or
// inverse (B->A, e^{+i}, *1/64). Per (b,kw) slab, 64-channel tile.
// ---------------------------------------------------------------------------
template <bool INV>
__global__ void __launch_bounds__(256) k_col_fft() {
    __shared__ float2 sr[64 * 32], si[64 * 32];  // [h][c2] (64 channels)
    __shared__ float2 root[64];
    int t = threadIdx.x;
    make_root(root, t);
    int slab = blockIdx.y;            // b*33 + kw
    int b = slab / 33, kw = slab % 33;
    int c0 = blockIdx.x * 64;
    const float* inr = INV ? g_Br : g_Ar;
    const float* ini = INV ? g_Bi : g_Ai;
    float* outr = INV ? g_Ar : g_Br;
    float* outi = INV ? g_Ai : g_Bi;
    float4* sr4 = (float4*)sr;
    float4* si4 = (float4*)si;
    for (int f = t; f < 1024; f += 256) {        // 64 rows * 16 float4
        int h = f >> 4, q = f & 15;
        size_t src = (((size_t)b * 64 + h) * 33 + kw) * 1024 + c0 + q * 4;
        sr4[f] = *(const float4*)(inr + src);
        si4[f] = *(const float4*)(ini + src);
    }
    __syncthreads();
    int c2 = t & 31;
    int kq = t >> 5;                  // 8 groups of 8 output bins
    for (int n = 0; n < 8; n++) {
        int kh = kq * 8 + n;
        float rx = 0.f, ry = 0.f, ix = 0.f, iy = 0.f;
        int j = 0;
        #pragma unroll
        for (int h = 0; h < 64; h++) {
            float2 tw = root[j];
            float s = INV ? -tw.y : tw.y;
            float2 xr = sr[h * 32 + c2];
            float2 xi = si[h * 32 + c2];
            rx += xr.x * tw.x + xi.x * s;
            ry += xr.y * tw.x + xi.y * s;
            ix += xi.x * tw.x - xr.x * s;
            iy += xi.y * tw.x - xr.y * s;
            j = (j + kh) & 63;
        }
        const float sc = 1.0f / 64.0f;
        size_t o = (((size_t)b * 64 + kh) * 33 + kw) * 1024 + c0 + 2 * c2;
        *(float2*)(outr + o) = make_float2(rx * sc, ry * sc);
        *(float2*)(outi + o) = make_float2(ix * sc, iy * sc);
    }
}

// ---------------------------------------------------------------------------
// K3: per-frequency-point block-diagonal complex MLP, in place on g_Br/g_Bi.
// Block tile: 32 points x 128 outputs for one channel-block kb.
// Thread micro-tile: 4 points x 4 outputs (r and i accumulators).
// ---------------------------------------------------------------------------
__global__ void __launch_bounds__(256) k_mlp(const float* __restrict__ w1,
                                             const float* __restrict__ b1,
                                             const float* __restrict__ w2,
                                             const float* __restrict__ b2) {
    __shared__ float xsr[32 * 128], xsi[32 * 128];   // x tile, reused for o1
    __shared__ float wsr[8 * 128], wsi[8 * 128];     // weight chunk
    int t = threadIdx.x;
    int kb = blockIdx.y;
    int p0 = blockIdx.x * 32;
    // load x tile [32 points][128 inputs]
    for (int f = t; f < 1024; f += 256) {            // 32 rows * 32 float4
        int p = f >> 5, q = f & 31;
        size_t src = ((size_t)(p0 + p)) * 1024 + kb * 128 + q * 4;
        *(float4*)(xsr + p * 128 + q * 4) = *(const float4*)(g_Br + src);
        *(float4*)(xsi + p * 128 + q * 4) = *(const float4*)(g_Bi + src);
    }
    int og = (t & 31) * 4;    // 4 output columns
    int pg = (t >> 5) * 4;    // 4 point rows
    float ar[4][4], ai[4][4];

    // ===== layer 1 =====
    {
        const float* br = b1 + kb * 128;
        const float* bi = b1 + 1024 + kb * 128;
        #pragma unroll
        for (int q = 0; q < 4; q++) {
            float bv = br[og + q], bw = bi[og + q];
            #pragma unroll
            for (int p = 0; p < 4; p++) { ar[p][q] = bv; ai[p][q] = bw; }
        }
        const float* wr = w1 + (size_t)kb * 16384;
        const float* wi = w1 + 131072 + (size_t)kb * 16384;
        for (int ci = 0; ci < 128; ci += 8) {
            __syncthreads();
            {
                int i = t >> 5, q = t & 31;
                *(float4*)(wsr + i * 128 + q * 4) = *(const float4*)(wr + (ci + i) * 128 + q * 4);
                *(float4*)(wsi + i * 128 + q * 4) = *(const float4*)(wi + (ci + i) * 128 + q * 4);
            }
            __syncthreads();
            #pragma unroll
            for (int i = 0; i < 8; i++) {
                float4 w4r = *(float4*)(wsr + i * 128 + og);
                float4 w4i = *(float4*)(wsi + i * 128 + og);
                float xrv[4], xiv[4];
                #pragma unroll
                for (int p = 0; p < 4; p++) {
                    xrv[p] = xsr[(pg + p) * 128 + ci + i];
                    xiv[p] = xsi[(pg + p) * 128 + ci + i];
                }
                float wrq[4] = {w4r.x, w4r.y, w4r.z, w4r.w};
                float wiq[4] = {w4i.x, w4i.y, w4i.z, w4i.w};
                #pragma unroll
                for (int p = 0; p < 4; p++)
                    #pragma unroll
                    for (int q = 0; q < 4; q++) {
                        ar[p][q] += xrv[p] * wrq[q] - xiv[p] * wiq[q];
                        ai[p][q] += xiv[p] * wrq[q] + xrv[p] * wiq[q];
                    }
            }
        }
    }
    __syncthreads();   // all layer-1 reads of xs done -> safe to overwrite with o1
    #pragma unroll
    for (int p = 0; p < 4; p++) {
        float4 vr = make_float4(fmaxf(ar[p][0], 0.f), fmaxf(ar[p][1], 0.f),
                                fmaxf(ar[p][2], 0.f), fmaxf(ar[p][3], 0.f));
        float4 vi = make_float4(fmaxf(ai[p][0], 0.f), fmaxf(ai[p][1], 0.f),
                                fmaxf(ai[p][2], 0.f), fmaxf(ai[p][3], 0.f));
        *(float4*)(xsr + (pg + p) * 128 + og) = vr;
        *(float4*)(xsi + (pg + p) * 128 + og) = vi;
    }

    // ===== layer 2 ===== (leading sync in chunk loop orders o1 writes)
    {
        const float* br = b2 + kb * 128;
        const float* bi = b2 + 1024 + kb * 128;
        #pragma unroll
        for (int q = 0; q < 4; q++) {
            float bv = br[og + q], bw = bi[og + q];
            #pragma unroll
            for (int p = 0; p < 4; p++) { ar[p][q] = bv; ai[p][q] = bw; }
        }
        const float* wr = w2 + (size_t)kb * 16384;
        const float* wi = w2 + 131072 + (size_t)kb * 16384;
        for (int ci = 0; ci < 128; ci += 8) {
            __syncthreads();
            {
                int i = t >> 5, q = t & 31;
                *(float4*)(wsr + i * 128 + q * 4) = *(const float4*)(wr + (ci + i) * 128 + q * 4);
                *(float4*)(wsi + i * 128 + q * 4) = *(const float4*)(wi + (ci + i) * 128 + q * 4);
            }
            __syncthreads();
            #pragma unroll
            for (int i = 0; i < 8; i++) {
                float4 w4r = *(float4*)(wsr + i * 128 + og);
                float4 w4i = *(float4*)(wsi + i * 128 + og);
                float xrv[4], xiv[4];
                #pragma unroll
                for (int p = 0; p < 4; p++) {
                    xrv[p] = xsr[(pg + p) * 128 + ci + i];
                    xiv[p] = xsi[(pg + p) * 128 + ci + i];
                }
                float wrq[4] = {w4r.x, w4r.y, w4r.z, w4r.w};
                float wiq[4] = {w4i.x, w4i.y, w4i.z, w4i.w};
                #pragma unroll
                for (int p = 0; p < 4; p++)
                    #pragma unroll
                    for (int q = 0; q < 4; q++) {
                        ar[p][q] += xrv[p] * wrq[q] - xiv[p] * wiq[q];
                        ai[p][q] += xiv[p] * wrq[q] + xrv[p] * wiq[q];
                    }
            }
        }
    }
    // softshrink epilogue, write back in place
    #pragma unroll
    for (int p = 0; p < 4; p++) {
        float4 vr = make_float4(softshrink(ar[p][0]), softshrink(ar[p][1]),
                                softshrink(ar[p][2]), softshrink(ar[p][3]));
        float4 vi = make_float4(softshrink(ai[p][0]), softshrink(ai[p][1]),
                                softshrink(ai[p][2]), softshrink(ai[p][3]));
        size_t o = ((size_t)(p0 + pg + p)) * 1024 + kb * 128 + og;
        *(float4*)(g_Br + o) = vr;
        *(float4*)(g_Bi + o) = vi;
    }
}

// ---------------------------------------------------------------------------
// K6: irfft along W (33 bins -> 64 real) + bias add.
// x[w] = Yr[0] + (-1)^w Yr[32] + sum_{k=1}^{31} 2(Yr[k]cos - Yi[k]sin)
// (imag of DC/Nyquist ignored, matching pocketfft/ducc c2r). No extra scale
// here: ortho 1/64 was applied in the inverse column FFT.
// ---------------------------------------------------------------------------
__global__ void __launch_bounds__(256) k_row_irfft(const float* __restrict__ x,
                                                   float* __restrict__ out) {
    __shared__ float2 syr[33 * 64], syi[33 * 64];   // [k][c2]
    __shared__ float2 root[64];
    int t = threadIdx.x;
    make_root(root, t);
    int slab = blockIdx.y;            // b*64 + h
    int c0 = blockIdx.x * 128;
    float4* r4 = (float4*)syr;
    float4* i4 = (float4*)syi;
    for (int f = t; f < 1056; f += 256) {           // 33 rows * 32 float4
        int k = f >> 5, q = f & 31;
        size_t src = ((size_t)slab * 33 + k) * 1024 + c0 + q * 4;
        r4[f] = *(const float4*)(g_Ar + src);
        i4[f] = *(const float4*)(g_Ai + src);
    }
    __syncthreads();
    int c2 = t & 63;
    int wq = t >> 6;
    float2 y0 = syr[c2];
    float2 y32 = syr[32 * 64 + c2];
    for (int n = 0; n < 16; n++) {
        int w = wq * 16 + n;
        float ax = 0.f, ay = 0.f;
        int j = w;                     // (1*w) & 63
        #pragma unroll
        for (int k = 1; k < 32; k++) {
            float2 tw = root[j];
            float2 yr = syr[k * 64 + c2];
            float2 yi = syi[k * 64 + c2];
            ax += yr.x * tw.x - yi.x * tw.y;
            ay += yr.y * tw.x - yi.y * tw.y;
            j = (j + w) & 63;
        }
        float sg = (w & 1) ? -1.f : 1.f;
        float rx = y0.x + sg * y32.x + 2.f * ax;
        float ry = y0.y + sg * y32.y + 2.f * ay;
        size_t o = ((size_t)slab * 64 + w) * 1024 + c0 + 2 * c2;
        float2 xb = *(const float2*)(x + o);
        *(float2*)(out + o) = make_float2(xb.x + rx, xb.y + ry);
    }
}

extern "C" void kernel_launch(void* const* d_in, const int* in_sizes, int n_in,
                              void* d_out, int out_size) {
    const float* x  = (const float*)d_in[0];
    const float* w1 = (const float*)d_in[1];
    const float* b1 = (const float*)d_in[2];
    const float* w2 = (const float*)d_in[3];
    const float* b2 = (const float*)d_in[4];
    float* out = (float*)d_out;

    k_row_rfft<<<dim3(8, 512), 256>>>(x);              // x -> A (spectral rows)
    k_col_fft<false><<<dim3(16, 264), 256>>>();        // A -> B (full fwd FFT, /64)
    k_mlp<<<dim3(528, 8), 256>>>(w1, b1, w2, b2);      // B -> B (block MLP, in place)
    k_col_fft<true><<<dim3(16, 264), 256>>>();         // B -> A (inv col FFT, /64)
    k_row_irfft<<<dim3(8, 512), 256>>>(x, out);        // A -> out (+bias)
}